// round 16
// baseline (speedup 1.0000x reference)
#include <cuda_runtime.h>
#include <cuda_fp16.h>
#include <math.h>
#include <stdint.h>

// ---------------------------------------------------------------------------
// Scratch (no allocation allowed)
// ---------------------------------------------------------------------------
#define MAX_TBD (2048*16*1024)
#define MAX_HALL ((2048+1)*16*1024)
#define MAX_BD   (16*1024)
#define MAX_NCHK 64
__device__ __half g_dh[MAX_TBD];        // delta fp16 (GEMM0 out)
__device__ __half g_ch[MAX_TBD];        // tanh(cand) fp16 if rh==0, else cand
__device__ float g_hall[MAX_HALL];      // fallback if d_out holds only outs
__device__ __half g_xh[MAX_TBD];        // x fp16
__device__ __half g_hh[MAX_TBD];        // h fp16 (written by scan)
__device__ __half g_wh[2*1024*1024];    // [W_delta ; W_x] fp16
__device__ __half g_woh[1024*1024];     // W_out fp16
__device__ float g_Abuf[MAX_NCHK*MAX_BD];
__device__ float g_Bbuf[MAX_NCHK*MAX_BD];
__device__ float g_hb[MAX_NCHK*MAX_BD];
__device__ int   g_rh_zero;

// ---------------------------------------------------------------------------
// Helpers
// ---------------------------------------------------------------------------
__device__ __forceinline__ uint32_t smem_u32(const void* p) {
    uint32_t a;
    asm("{ .reg .u64 t; cvta.to.shared.u64 t, %1; cvt.u32.u64 %0, t; }" : "=r"(a) : "l"(p));
    return a;
}

#define LDSM_X4(r0, r1, r2, r3, addr) \
    asm volatile("ldmatrix.sync.aligned.m8n8.x4.shared.b16 {%0,%1,%2,%3}, [%4];" \
                 : "=r"(r0), "=r"(r1), "=r"(r2), "=r"(r3) : "r"(addr))

#define MMAF16(c, a, b0, b1) \
    asm volatile("mma.sync.aligned.m16n8k16.row.col.f32.f16.f16.f32 " \
                 "{%0,%1,%2,%3},{%4,%5,%6,%7},{%8,%9},{%0,%1,%2,%3};" \
                 : "+f"((c)[0]), "+f"((c)[1]), "+f"((c)[2]), "+f"((c)[3]) \
                 : "r"((a)[0]), "r"((a)[1]), "r"((a)[2]), "r"((a)[3]), \
                   "r"(b0), "r"(b1))

#define CP16(dst, src) \
    asm volatile("cp.async.cg.shared.global [%0], [%1], 16;" :: "r"(dst), "l"(src) : "memory")
#define CP_COMMIT() asm volatile("cp.async.commit_group;" ::: "memory")
#define CP_WAIT2()  asm volatile("cp.async.wait_group 2;" ::: "memory")
#define CP_WAIT1()  asm volatile("cp.async.wait_group 1;" ::: "memory")
#define CP_WAIT0()  asm volatile("cp.async.wait_group 0;" ::: "memory")

// ---------------------------------------------------------------------------
// One fused fp32 -> fp16 conversion for x + the three weights.
// Block 0 additionally computes the r_h==0 flag (no extra launch).
// ---------------------------------------------------------------------------
__global__ void cvt_all(const float* __restrict__ x,
                        const float* __restrict__ wd,
                        const float* __restrict__ wx,
                        const float* __restrict__ wo,
                        const float* __restrict__ r_h,
                        __half* __restrict__ xh,
                        __half* __restrict__ wh,
                        __half* __restrict__ woh,
                        int n4x, int n4w, int D)
{
    int i = blockIdx.x * blockDim.x + threadIdx.x;
    const float* src = nullptr;
    __half* dst = nullptr;
    int off = 0;
    bool act = true;
    if (i < n4x) {
        src = x; dst = xh; off = i;
    } else {
        int w = i - n4x;
        int which = w / n4w;
        if (which >= 3) act = false;
        else {
            off = w - which * n4w;
            if (which == 0)      { src = wd; dst = wh; }
            else if (which == 1) { src = wx; dst = wh + (size_t)n4w * 4; }
            else                 { src = wo; dst = woh; }
        }
    }
    if (act) {
        float4 f = ((const float4*)src)[off];
        ((__half2*)dst)[2*off]   = __halves2half2(__float2half_rn(f.x), __float2half_rn(f.y));
        ((__half2*)dst)[2*off+1] = __halves2half2(__float2half_rn(f.z), __float2half_rn(f.w));
    }
    if (blockIdx.x == 0) {
        int nz = 0;
        for (int k = threadIdx.x; k < D; k += blockDim.x)
            if (r_h[k] != 0.f) nz = 1;
        int any = __syncthreads_or(nz);
        if (threadIdx.x == 0) g_rh_zero = any ? 0 : 1;
    }
}

// ---------------------------------------------------------------------------
// Persistent fp16 1-pass HMMA GEMM: C = epi( A[M,K] @ B[N,K]^T ), fp32 accum.
// Grid = 2/SM persistent CTAs, each walking tiles with stride gridDim.x.
// CTA tile 128x128, 8 warps (2x4), warp tile 64x32, BK=32, cp.async 4-stage
// ring over a GLOBAL chunk stream spanning all the CTA's tiles — the pipeline
// never drains between tiles. Padded smem rows: 32 fp16 + 16B pad = 80B.
// MODE 0: n0 <  nSplit -> fp16( sigmoid(acc+bias0) ) -> out0 (delta)
//         n0 >= nSplit -> fp16( g_rh_zero ? tanh(acc+bias1) : acc+bias1 ) -> out1
// MODE 1: compete(hsrc fp16) * silu(acc) -> out0 (fp32, streaming store)
// ---------------------------------------------------------------------------
#define STG_B    10240
#define STAGE_SZ 20480
#define NSTAGE   4
#define GSMEM (NSTAGE * STAGE_SZ)

template <int MODE>
__global__ void __launch_bounds__(256, 2) gemm_f16(
    const __half* __restrict__ Ah,
    const __half* __restrict__ Bh,
    const float* __restrict__ bias0,
    const float* __restrict__ bias1,
    void* __restrict__ out0v,
    void* __restrict__ out1v,
    const __half* __restrict__ hsrc,
    int K, int ldC, int nSplit, int nTx, int nTiles)
{
    extern __shared__ __align__(1024) char smem[];
    const uint32_t sb = smem_u32(smem);
    const int tid = threadIdx.x, wid = tid >> 5, lid = tid & 31;

    const int lr  = tid >> 1;              // row within tile (0..127)
    const int lc2 = (tid & 1) * 16;        // k offset (halves)
    const uint32_t dOff = (uint32_t)lr * 80 + (uint32_t)(tid & 1) * 32;

    const int wm = wid >> 2, wn = wid & 3;
    const uint32_t aoff = ((uint32_t)((lid & 7) + ((lid >> 3) & 1) * 8) + (uint32_t)wm * 64) * 80
                        + (uint32_t)(lid >> 4) * 16;
    const uint32_t boff = ((uint32_t)((lid & 7) + (lid >> 4) * 8) + (uint32_t)wn * 32) * 80
                        + (uint32_t)((lid >> 3) & 1) * 16;

    const int NCH = K / 32;
    const int G = gridDim.x;
    const int nMy = (nTiles - (int)blockIdx.x + G - 1) / G;
    if (nMy <= 0) return;
    const int Jtot = nMy * NCH;

    // producer-side cursor
    int i_ch = 0, i_t = blockIdx.x;
    auto issue_cur = [&]() {
        const int tm0 = (i_t / nTx) * 128;
        const int tn0 = (i_t % nTx) * 128;
        const size_t ko = (size_t)i_ch * 32;
        const __half* a1 = Ah + (size_t)(tm0 + lr) * K + lc2 + ko;
        const __half* b1 = Bh + (size_t)(tn0 + lr) * K + lc2 + ko;
        uint32_t d = sb + (uint32_t)((i_ch + 0) & 0) * 0;  // placeholder (stage below)
        (void)d;
    };
    (void)issue_cur;

    // producer issue with explicit stage (global chunk index j)
    int p_ch = 0, p_t = blockIdx.x;
    int p_m0 = (p_t / nTx) * 128, p_n0 = (p_t % nTx) * 128;
    auto issue = [&](int j) {
        const uint32_t stb = sb + (uint32_t)(j & (NSTAGE - 1)) * STAGE_SZ;
        const size_t ko = (size_t)p_ch * 32;
        const __half* a1 = Ah + (size_t)(p_m0 + lr) * K + lc2 + ko;
        const __half* b1 = Bh + (size_t)(p_n0 + lr) * K + lc2 + ko;
        uint32_t d = stb + dOff;
        CP16(d,            a1);  CP16(d + 16,            a1 + 8);
        CP16(d + STG_B,    b1);  CP16(d + STG_B + 16,    b1 + 8);
        if (++p_ch == NCH) {
            p_ch = 0;
            p_t += G;
            p_m0 = (p_t / nTx) * 128;
            p_n0 = (p_t % nTx) * 128;
        }
    };

    float acc[4][4][4];
#pragma unroll
    for (int i = 0; i < 4; ++i)
#pragma unroll
        for (int j = 0; j < 4; ++j)
#pragma unroll
            for (int q = 0; q < 4; ++q) acc[i][j][q] = 0.f;

    // prologue: up to 3 chunks in flight
    {
        int npro = Jtot < 3 ? Jtot : 3;
        for (int j = 0; j < npro; ++j) { issue(j); CP_COMMIT(); }
    }

    // consumer-side tile cursor
    int c_ch = 0, c_t = blockIdx.x;

#pragma unroll 1
    for (int j = 0; j < Jtot; ++j) {
        if (j + 2 < Jtot)      CP_WAIT2();
        else if (j + 1 < Jtot) CP_WAIT1();
        else                   CP_WAIT0();
        __syncthreads();
        if (j + 3 < Jtot) { issue(j + 3); CP_COMMIT(); }

        const uint32_t stA = sb + (uint32_t)(j & (NSTAGE - 1)) * STAGE_SZ;
#pragma unroll
        for (int kk = 0; kk < 2; ++kk) {
            const uint32_t kof = (uint32_t)kk * 32;
            uint32_t bh[4][2];
            LDSM_X4(bh[0][0], bh[0][1], bh[1][0], bh[1][1],
                    stA + STG_B + boff + kof);
            LDSM_X4(bh[2][0], bh[2][1], bh[3][0], bh[3][1],
                    stA + STG_B + boff + 1280 + kof);
            uint32_t ah[4][4];
#pragma unroll
            for (int mi = 0; mi < 4; ++mi)
                LDSM_X4(ah[mi][0], ah[mi][1], ah[mi][2], ah[mi][3],
                        stA + aoff + (uint32_t)mi * 1280 + kof);
#pragma unroll
            for (int mi = 0; mi < 4; ++mi)
#pragma unroll
                for (int nj = 0; nj < 4; ++nj)
                    MMAF16(acc[mi][nj], ah[mi], bh[nj][0], bh[nj][1]);
        }

        if (++c_ch < NCH) continue;
        c_ch = 0;

        // ---- epilogue for tile c_t (cp.async of next tile already in flight) ----
        const int m0 = (c_t / nTx) * 128;
        const int n0 = (c_t % nTx) * 128;
        const int qr = lid >> 2;
        const int qc = 2 * (lid & 3);
        const int gcol0 = n0 + wn * 32;

        if (MODE == 0) {
            const int sel = (n0 >= nSplit);
            const int rz = g_rh_zero;
            const float* bias = sel ? bias1 : bias0;
            __half* Cout = sel ? (__half*)out1v : (__half*)out0v;
            const int colBase = gcol0 - sel * nSplit;
            float bv[8];
#pragma unroll
            for (int nj = 0; nj < 4; ++nj) {
                float2 t = *(const float2*)(bias + colBase + nj * 8 + qc);
                bv[2*nj] = t.x; bv[2*nj+1] = t.y;
            }
#pragma unroll
            for (int mi = 0; mi < 4; ++mi) {
                const int r0 = m0 + wm * 64 + mi * 16 + qr;
#pragma unroll
                for (int nj = 0; nj < 4; ++nj) {
                    const int c = colBase + nj * 8 + qc;
                    float v0 = acc[mi][nj][0] + bv[2*nj];
                    float v1 = acc[mi][nj][1] + bv[2*nj+1];
                    float v2 = acc[mi][nj][2] + bv[2*nj];
                    float v3 = acc[mi][nj][3] + bv[2*nj+1];
                    if (!sel) {
                        v0 = 1.f / (1.f + __expf(-v0));
                        v1 = 1.f / (1.f + __expf(-v1));
                        v2 = 1.f / (1.f + __expf(-v2));
                        v3 = 1.f / (1.f + __expf(-v3));
                    } else if (rz) {
                        v0 = tanhf(v0); v1 = tanhf(v1);
                        v2 = tanhf(v2); v3 = tanhf(v3);
                    }
                    *(__half2*)(Cout + (size_t)r0 * ldC + c) =
                        __halves2half2(__float2half_rn(v0), __float2half_rn(v1));
                    *(__half2*)(Cout + (size_t)(r0 + 8) * ldC + c) =
                        __halves2half2(__float2half_rn(v2), __float2half_rn(v3));
                }
            }
        } else {
            float* Cout = (float*)out0v;
#pragma unroll
            for (int mi = 0; mi < 4; ++mi) {
                const int r0 = m0 + wm * 64 + mi * 16 + qr;
                const int r1 = r0 + 8;
                float h0v[8], h1v[8];
#pragma unroll
                for (int nj = 0; nj < 4; ++nj) {
                    const int c = gcol0 + nj * 8 + qc;
                    float2 t0 = __half22float2(*(const __half2*)(hsrc + (size_t)r0 * ldC + c));
                    float2 t1 = __half22float2(*(const __half2*)(hsrc + (size_t)r1 * ldC + c));
                    h0v[2*nj] = t0.x; h0v[2*nj+1] = t0.y;
                    h1v[2*nj] = t1.x; h1v[2*nj+1] = t1.y;
                }
                float mx0 = h0v[0], mx1 = h1v[0];
#pragma unroll
                for (int k = 1; k < 8; ++k) {
                    mx0 = fmaxf(mx0, h0v[k]);
                    mx1 = fmaxf(mx1, h1v[k]);
                }
                mx0 = fmaxf(mx0, __shfl_xor_sync(0xffffffffu, mx0, 1));
                mx0 = fmaxf(mx0, __shfl_xor_sync(0xffffffffu, mx0, 2));
                mx1 = fmaxf(mx1, __shfl_xor_sync(0xffffffffu, mx1, 1));
                mx1 = fmaxf(mx1, __shfl_xor_sync(0xffffffffu, mx1, 2));
                float s0 = 0.f, s1 = 0.f;
#pragma unroll
                for (int k = 0; k < 8; ++k) {
                    h0v[k] = __expf(h0v[k] - mx0); s0 += h0v[k];
                    h1v[k] = __expf(h1v[k] - mx1); s1 += h1v[k];
                }
                s0 += __shfl_xor_sync(0xffffffffu, s0, 1);
                s0 += __shfl_xor_sync(0xffffffffu, s0, 2);
                s1 += __shfl_xor_sync(0xffffffffu, s1, 1);
                s1 += __shfl_xor_sync(0xffffffffu, s1, 2);
                const float inv0 = 1.f / s0, inv1 = 1.f / s1;
#pragma unroll
                for (int nj = 0; nj < 4; ++nj) {
                    const int c = gcol0 + nj * 8 + qc;
                    float y0 = acc[mi][nj][0], y1 = acc[mi][nj][1];
                    float y2 = acc[mi][nj][2], y3 = acc[mi][nj][3];
                    float v0 = (h0v[2*nj]   * inv0) * (y0 / (1.f + __expf(-y0)));
                    float v1 = (h0v[2*nj+1] * inv0) * (y1 / (1.f + __expf(-y1)));
                    float v2 = (h1v[2*nj]   * inv1) * (y2 / (1.f + __expf(-y2)));
                    float v3 = (h1v[2*nj+1] * inv1) * (y3 / (1.f + __expf(-y3)));
                    __stcs((float2*)(Cout + (size_t)r0 * ldC + c), make_float2(v0, v1));
                    __stcs((float2*)(Cout + (size_t)r1 * ldC + c), make_float2(v2, v3));
                }
            }
        }

        c_t += G;
#pragma unroll
        for (int i = 0; i < 4; ++i)
#pragma unroll
            for (int jj = 0; jj < 4; ++jj)
#pragma unroll
                for (int q = 0; q < 4; ++q) acc[i][jj][q] = 0.f;
    }
}

// ---------------------------------------------------------------------------
// Scan: parallel fast path when r_h == 0 (linear recurrence), else sequential.
// tc = tanh(cand) is precomputed by GEMM0's epilogue -> scans are pure fma.
// ---------------------------------------------------------------------------

// Phase 1: per-chunk affine composition (A,B): h_end = A*h_start + B
__global__ void scan_part1(const __half* __restrict__ delta,
                           const __half* __restrict__ tc,
                           float* __restrict__ Abuf,
                           float* __restrict__ Bbuf,
                           int BD, int CHK)
{
    if (!g_rh_zero) return;
    const int l2 = blockIdx.x * blockDim.x + threadIdx.x;
    const int cc = blockIdx.y;
    const int BD2 = BD >> 1;
    const __half2* dp = (const __half2*)delta + (size_t)cc * CHK * BD2 + l2;
    const __half2* cp = (const __half2*)tc    + (size_t)cc * CHK * BD2 + l2;
    float Ax = 1.f, Ay = 1.f, Bx = 0.f, By = 0.f;
#pragma unroll 8
    for (int u = 0; u < CHK; ++u) {
        float2 d = __half22float2(dp[(size_t)u * BD2]);
        float2 t = __half22float2(cp[(size_t)u * BD2]);
        float ax = 1.f - d.x, ay = 1.f - d.y;
        Ax *= ax; Ay *= ay;
        Bx = fmaf(ax, Bx, d.x * t.x);
        By = fmaf(ay, By, d.y * t.y);
    }
    *(float2*)(Abuf + (size_t)cc * BD + 2 * l2) = make_float2(Ax, Ay);
    *(float2*)(Bbuf + (size_t)cc * BD + 2 * l2) = make_float2(Bx, By);
}

// Phase 2 (fast path): boundary scan, all NCHK (A,B) prefetched to registers.
// Fallback path (r_h != 0): full sequential scan folded in (same BD lanes).
__global__ void scan_part2(const float* __restrict__ Abuf,
                           const float* __restrict__ Bbuf,
                           const float* __restrict__ h0,
                           float* __restrict__ hb,
                           float* __restrict__ h_all,
                           const __half* __restrict__ delta,
                           const __half* __restrict__ cand,
                           const float* __restrict__ r_h,
                           __half* __restrict__ hhi,
                           int BD, int NCHK, int T, int D)
{
    const int lane = blockIdx.x * blockDim.x + threadIdx.x;
    if (g_rh_zero) {
        float h = h0[lane];
        h_all[lane] = h;
        if (NCHK <= 32) {
            float Ar[32], Br[32];
#pragma unroll
            for (int cc = 0; cc < 32; ++cc) {
                if (cc < NCHK) {
                    Ar[cc] = Abuf[(size_t)cc * BD + lane];
                    Br[cc] = Bbuf[(size_t)cc * BD + lane];
                }
            }
#pragma unroll
            for (int cc = 0; cc < 32; ++cc) {
                if (cc < NCHK) {
                    hb[(size_t)cc * BD + lane] = h;
                    h = fmaf(Ar[cc], h, Br[cc]);
                }
            }
        } else {
            for (int cc = 0; cc < NCHK; ++cc) {
                hb[(size_t)cc * BD + lane] = h;
                h = fmaf(Abuf[(size_t)cc * BD + lane], h, Bbuf[(size_t)cc * BD + lane]);
            }
        }
    } else {
        float h = h0[lane];
        float rh = r_h[lane % D];
        h_all[lane] = h;
        for (int t = 0; t < T; ++t) {
            float d = __half2float(delta[(size_t)t * BD + lane]);
            float c = __half2float(cand[(size_t)t * BD + lane]);
            float cv = tanhf(fmaf(rh, h, c));
            h = fmaf(d, cv - h, h);
            h_all[BD + (size_t)t * BD + lane] = h;
            hhi[(size_t)t * BD + lane] = __float2half_rn(h);
        }
    }
}

// Phase 3: recompute within chunk from boundary, write h_all fp32 + h fp16
__global__ void scan_part3(const __half* __restrict__ delta,
                           const __half* __restrict__ tc,
                           const float* __restrict__ hb,
                           float* __restrict__ h_all,
                           __half* __restrict__ hhi,
                           int BD, int CHK)
{
    if (!g_rh_zero) return;
    const int l2 = blockIdx.x * blockDim.x + threadIdx.x;
    const int cc = blockIdx.y;
    const int BD2 = BD >> 1;
    const __half2* dp = (const __half2*)delta + (size_t)cc * CHK * BD2 + l2;
    const __half2* cp = (const __half2*)tc    + (size_t)cc * CHK * BD2 + l2;
    __half2* hp16 = (__half2*)hhi + (size_t)cc * CHK * BD2 + l2;
    float2* hp32 = (float2*)(h_all + BD) + (size_t)cc * CHK * BD2 + l2;
    float2 h = *(const float2*)(hb + (size_t)cc * BD + 2 * l2);
#pragma unroll 8
    for (int u = 0; u < CHK; ++u) {
        float2 d = __half22float2(__ldcs(dp + (size_t)u * BD2));
        float2 t = __half22float2(__ldcs(cp + (size_t)u * BD2));
        h.x = fmaf(d.x, t.x - h.x, h.x);
        h.y = fmaf(d.y, t.y - h.y, h.y);
        __stcs(hp32 + (size_t)u * BD2, h);
        hp16[(size_t)u * BD2] = __halves2half2(__float2half_rn(h.x), __float2half_rn(h.y));
    }
}

// ---------------------------------------------------------------------------
extern "C" void kernel_launch(void* const* d_in, const int* in_sizes, int n_in,
                              void* d_out, int out_size)
{
    const float* x       = (const float*)d_in[0];
    const float* h0      = (const float*)d_in[1];
    const float* W_x     = (const float*)d_in[2];
    const float* r_h     = (const float*)d_in[3];
    const float* b       = (const float*)d_in[4];
    const float* W_delta = (const float*)d_in[5];
    const float* b_delta = (const float*)d_in[6];
    const float* W_out   = (const float*)d_in[7];
    float* out = (float*)d_out;

    int D  = (int)(sqrt((double)in_sizes[2]) + 0.5);
    int Bn = in_sizes[1] / D;
    int Tn = in_sizes[0] / (Bn * D);
    int BD = Bn * D;
    int M  = Tn * Bn;
    int DD = D * D;

    float *ghall, *gA, *gB, *ghb;
    __half *gdh, *gch, *xh, *hh, *wh, *woh;
    cudaGetSymbolAddress((void**)&gdh,   g_dh);
    cudaGetSymbolAddress((void**)&gch,   g_ch);
    cudaGetSymbolAddress((void**)&ghall, g_hall);
    cudaGetSymbolAddress((void**)&xh,    g_xh);
    cudaGetSymbolAddress((void**)&hh,    g_hh);
    cudaGetSymbolAddress((void**)&wh,    g_wh);
    cudaGetSymbolAddress((void**)&woh,   g_woh);
    cudaGetSymbolAddress((void**)&gA,    g_Abuf);
    cudaGetSymbolAddress((void**)&gB,    g_Bbuf);
    cudaGetSymbolAddress((void**)&ghb,   g_hb);

    float *hall, *outs;
    long need_both = (long)(Tn + 1) * BD + (long)M * D;
    if ((long)out_size >= need_both) {
        hall = out;
        outs = out + (size_t)(Tn + 1) * BD;
    } else {
        hall = ghall;
        outs = out;
    }

    cudaFuncSetAttribute(gemm_f16<0>, cudaFuncAttributeMaxDynamicSharedMemorySize, GSMEM);
    cudaFuncSetAttribute(gemm_f16<1>, cudaFuncAttributeMaxDynamicSharedMemorySize, GSMEM);

    // Phase 0: one fused conversion launch (also computes r_h flag in block 0)
    int n4x = (M * D) / 4;
    int n4w = DD / 4;
    int n4tot = n4x + 3 * n4w;
    cvt_all<<<(n4tot + 255) / 256, 256>>>(x, W_delta, W_x, W_out, r_h,
                                          xh, wh, woh, n4x, n4w, D);

    const int PGRID = 304;   // 2 CTAs/SM on 152-SM GB300 (persistent)

    // Phase 1: fused delta|tc GEMM (N = 2D, split at D), fp16 outputs
    {
        int nTx = 2 * D / 128;
        int nTiles = nTx * (M / 128);
        int grid = nTiles < PGRID ? nTiles : PGRID;
        gemm_f16<0><<<grid, 256, GSMEM>>>(
            xh, wh, b_delta, b, gdh, gch, nullptr, D, D, D, nTx, nTiles);
    }

    // Phase 2: scan — parallel chunked fast path (r_h==0); sequential fallback
    // folded into scan_part2.
    {
        int CHK = 64;
        while (Tn % CHK) CHK >>= 1;
        int NCHK = Tn / CHK;
        if (NCHK > MAX_NCHK) { CHK = Tn / MAX_NCHK; NCHK = MAX_NCHK; }
        dim3 gch2(BD / 512, NCHK);          // 2 lanes per thread
        scan_part1<<<gch2, 256>>>(gdh, gch, gA, gB, BD, CHK);
        scan_part2<<<BD / 256, 256>>>(gA, gB, h0, ghb, hall,
                                      gdh, gch, r_h, hh, BD, NCHK, Tn, D);
        scan_part3<<<gch2, 256>>>(gdh, gch, ghb, hall, hh, BD, CHK);
    }

    // Phase 3: output GEMM with fused compete-softmax + silu epilogue
    {
        int nTx = D / 128;
        int nTiles = nTx * (M / 128);
        int grid = nTiles < PGRID ? nTiles : PGRID;
        gemm_f16<1><<<grid, 256, GSMEM>>>(
            hh, woh, nullptr, nullptr, outs, nullptr, hh, D, D, 0, nTx, nTiles);
    }
}

// round 17
// speedup vs baseline: 1.0614x; 1.0614x over previous
#include <cuda_runtime.h>
#include <cuda_fp16.h>
#include <math.h>
#include <stdint.h>

// ---------------------------------------------------------------------------
// Scratch (no allocation allowed)
// ---------------------------------------------------------------------------
#define MAX_TBD (2048*16*1024)
#define MAX_HALL ((2048+1)*16*1024)
#define MAX_BD   (16*1024)
#define MAX_NCHK 64
__device__ __half g_dh[MAX_TBD];        // delta fp16 (GEMM0 out)
__device__ __half g_ch[MAX_TBD];        // tanh(cand) fp16 if rh==0, else cand
__device__ float g_hall[MAX_HALL];      // fallback if d_out holds only outs
__device__ __half g_xh[MAX_TBD];        // x fp16
__device__ __half g_hh[MAX_TBD];        // h fp16 (written by scan)
__device__ __half g_wh[2*1024*1024];    // [W_delta ; W_x] fp16
__device__ __half g_woh[1024*1024];     // W_out fp16
__device__ float g_Abuf[MAX_NCHK*MAX_BD];
__device__ float g_Bbuf[MAX_NCHK*MAX_BD];
__device__ float g_hb[MAX_NCHK*MAX_BD];
__device__ int   g_rh_zero;

// ---------------------------------------------------------------------------
// Helpers
// ---------------------------------------------------------------------------
__device__ __forceinline__ uint32_t smem_u32(const void* p) {
    uint32_t a;
    asm("{ .reg .u64 t; cvta.to.shared.u64 t, %1; cvt.u32.u64 %0, t; }" : "=r"(a) : "l"(p));
    return a;
}

#define LDSM_X4(r0, r1, r2, r3, addr) \
    asm volatile("ldmatrix.sync.aligned.m8n8.x4.shared.b16 {%0,%1,%2,%3}, [%4];" \
                 : "=r"(r0), "=r"(r1), "=r"(r2), "=r"(r3) : "r"(addr))

#define MMAF16(c, a, b0, b1) \
    asm volatile("mma.sync.aligned.m16n8k16.row.col.f32.f16.f16.f32 " \
                 "{%0,%1,%2,%3},{%4,%5,%6,%7},{%8,%9},{%0,%1,%2,%3};" \
                 : "+f"((c)[0]), "+f"((c)[1]), "+f"((c)[2]), "+f"((c)[3]) \
                 : "r"((a)[0]), "r"((a)[1]), "r"((a)[2]), "r"((a)[3]), \
                   "r"(b0), "r"(b1))

#define CP16(dst, src) \
    asm volatile("cp.async.cg.shared.global [%0], [%1], 16;" :: "r"(dst), "l"(src) : "memory")
#define CP_COMMIT() asm volatile("cp.async.commit_group;" ::: "memory")
#define CP_WAIT2()  asm volatile("cp.async.wait_group 2;" ::: "memory")
#define CP_WAIT1()  asm volatile("cp.async.wait_group 1;" ::: "memory")
#define CP_WAIT0()  asm volatile("cp.async.wait_group 0;" ::: "memory")

// ---------------------------------------------------------------------------
// One fused fp32 -> fp16 conversion for x + the three weights.
// Each thread converts TWO independent float4s (MLP=2, half the grid).
// Block 0 additionally computes the r_h==0 flag (no extra launch).
// ---------------------------------------------------------------------------
__device__ __forceinline__ void cvt_one(const float* __restrict__ x,
                                        const float* __restrict__ wd,
                                        const float* __restrict__ wx,
                                        const float* __restrict__ wo,
                                        __half* __restrict__ xh,
                                        __half* __restrict__ wh,
                                        __half* __restrict__ woh,
                                        int n4x, int n4w, int i,
                                        const float4*& srcp, __half2*& dstp)
{
    srcp = nullptr; dstp = nullptr;
    const float* src; __half* dst; int off;
    if (i < n4x) {
        src = x; dst = xh; off = i;
    } else {
        int w = i - n4x;
        int which = w / n4w;
        if (which >= 3) return;
        off = w - which * n4w;
        if (which == 0)      { src = wd; dst = wh; }
        else if (which == 1) { src = wx; dst = wh + (size_t)n4w * 4; }
        else                 { src = wo; dst = woh; }
    }
    srcp = (const float4*)src + off;
    dstp = (__half2*)dst + 2 * (size_t)off;
}

__global__ void cvt_all(const float* __restrict__ x,
                        const float* __restrict__ wd,
                        const float* __restrict__ wx,
                        const float* __restrict__ wo,
                        const float* __restrict__ r_h,
                        __half* __restrict__ xh,
                        __half* __restrict__ wh,
                        __half* __restrict__ woh,
                        int n4x, int n4w, int D, int half_n)
{
    int i0 = blockIdx.x * blockDim.x + threadIdx.x;
    int i1 = i0 + half_n;

    const float4 *s0, *s1; __half2 *d0, *d1;
    cvt_one(x, wd, wx, wo, xh, wh, woh, n4x, n4w, i0, s0, d0);
    cvt_one(x, wd, wx, wo, xh, wh, woh, n4x, n4w, i1, s1, d1);

    float4 f0, f1;
    if (s0) f0 = *s0;          // both loads issued before conversions
    if (s1) f1 = *s1;
    if (s0) {
        d0[0] = __halves2half2(__float2half_rn(f0.x), __float2half_rn(f0.y));
        d0[1] = __halves2half2(__float2half_rn(f0.z), __float2half_rn(f0.w));
    }
    if (s1) {
        d1[0] = __halves2half2(__float2half_rn(f1.x), __float2half_rn(f1.y));
        d1[1] = __halves2half2(__float2half_rn(f1.z), __float2half_rn(f1.w));
    }

    if (blockIdx.x == 0) {
        int nz = 0;
        for (int k = threadIdx.x; k < D; k += blockDim.x)
            if (r_h[k] != 0.f) nz = 1;
        int any = __syncthreads_or(nz);
        if (threadIdx.x == 0) g_rh_zero = any ? 0 : 1;
    }
}

// ---------------------------------------------------------------------------
// fp16 1-pass HMMA GEMM: C = epi( A[M,K] @ B[N,K]^T ), fp32 accum.
// CTA 128x128, 8 warps (2x4), warp tile 64x32, BK=32, cp.async 4-stage ring,
// one __syncthreads per chunk. Padded smem rows: 32 fp16 + 16B pad = 80B.
// MODE 0: n0 <  nSplit -> fp16( sigmoid(acc+bias0) ) -> out0 (delta)
//         n0 >= nSplit -> fp16( g_rh_zero ? tanh(acc+bias1) : acc+bias1 ) -> out1
// MODE 1: compete(hsrc fp16) * silu(acc) -> out0 (fp32, streaming store)
// ---------------------------------------------------------------------------
#define STG_B    10240
#define STAGE_SZ 20480
#define NSTAGE   4
#define GSMEM (NSTAGE * STAGE_SZ)

template <int MODE>
__global__ void __launch_bounds__(256, 2) gemm_f16(
    const __half* __restrict__ Ah,
    const __half* __restrict__ Bh,
    const float* __restrict__ bias0,
    const float* __restrict__ bias1,
    void* __restrict__ out0v,
    void* __restrict__ out1v,
    const __half* __restrict__ hsrc,
    int K, int ldC, int nSplit)
{
    extern __shared__ __align__(1024) char smem[];
    const uint32_t sb = smem_u32(smem);
    const int tid = threadIdx.x, wid = tid >> 5, lid = tid & 31;
    const int m0 = blockIdx.y * 128;
    const int n0 = blockIdx.x * 128;

    const size_t aOff = (size_t)(m0 + (tid >> 1)) * K + (size_t)(tid & 1) * 16;
    const size_t bOff = (size_t)(n0 + (tid >> 1)) * K + (size_t)(tid & 1) * 16;
    const uint32_t dOff = (uint32_t)(tid >> 1) * 80 + (uint32_t)(tid & 1) * 32;

    const int wm = wid >> 2, wn = wid & 3;
    const uint32_t aoff = ((uint32_t)((lid & 7) + ((lid >> 3) & 1) * 8) + (uint32_t)wm * 64) * 80
                        + (uint32_t)(lid >> 4) * 16;
    const uint32_t boff = ((uint32_t)((lid & 7) + (lid >> 4) * 8) + (uint32_t)wn * 32) * 80
                        + (uint32_t)((lid >> 3) & 1) * 16;

    float acc[4][4][4];
#pragma unroll
    for (int i = 0; i < 4; ++i)
#pragma unroll
        for (int j = 0; j < 4; ++j)
#pragma unroll
            for (int q = 0; q < 4; ++q) acc[i][j][q] = 0.f;

    const int NCH = K / 32;

    auto issue = [&](int ch, int s) {
        const uint32_t stb = sb + (uint32_t)s * STAGE_SZ;
        const size_t ko = (size_t)ch * 32;
        const __half* a1 = Ah + aOff + ko;
        const __half* b1 = Bh + bOff + ko;
        uint32_t d = stb + dOff;
        CP16(d,            a1);  CP16(d + 16,            a1 + 8);
        CP16(d + STG_B,    b1);  CP16(d + STG_B + 16,    b1 + 8);
    };

    issue(0, 0); CP_COMMIT();
    issue(1, 1); CP_COMMIT();
    issue(2, 2); CP_COMMIT();

#pragma unroll 1
    for (int ch = 0; ch < NCH; ++ch) {
        const int s = ch & (NSTAGE - 1);
        if (ch + 2 < NCH)      CP_WAIT2();
        else if (ch + 1 < NCH) CP_WAIT1();
        else                   CP_WAIT0();
        __syncthreads();
        if (ch + 3 < NCH) { issue(ch + 3, (ch + 3) & (NSTAGE - 1)); CP_COMMIT(); }

        const uint32_t stA = sb + (uint32_t)s * STAGE_SZ;
#pragma unroll
        for (int kk = 0; kk < 2; ++kk) {
            const uint32_t kof = (uint32_t)kk * 32;
            uint32_t bh[4][2];
            LDSM_X4(bh[0][0], bh[0][1], bh[1][0], bh[1][1],
                    stA + STG_B + boff + kof);
            LDSM_X4(bh[2][0], bh[2][1], bh[3][0], bh[3][1],
                    stA + STG_B + boff + 1280 + kof);
            uint32_t ah[4][4];
#pragma unroll
            for (int mi = 0; mi < 4; ++mi)
                LDSM_X4(ah[mi][0], ah[mi][1], ah[mi][2], ah[mi][3],
                        stA + aoff + (uint32_t)mi * 1280 + kof);
#pragma unroll
            for (int mi = 0; mi < 4; ++mi)
#pragma unroll
                for (int nj = 0; nj < 4; ++nj)
                    MMAF16(acc[mi][nj], ah[mi], bh[nj][0], bh[nj][1]);
        }
    }

    // ---- epilogue ----
    const int qr = lid >> 2;       // 0..7
    const int qc = 2 * (lid & 3);  // 0,2,4,6
    const int gcol0 = n0 + wn * 32;

    if (MODE == 0) {
        const int sel = (n0 >= nSplit);
        const int rz = g_rh_zero;
        const float* bias = sel ? bias1 : bias0;
        __half* Cout = sel ? (__half*)out1v : (__half*)out0v;
        const int colBase = gcol0 - sel * nSplit;
        float bv[8];
#pragma unroll
        for (int nj = 0; nj < 4; ++nj) {
            float2 t = *(const float2*)(bias + colBase + nj * 8 + qc);
            bv[2*nj] = t.x; bv[2*nj+1] = t.y;
        }
#pragma unroll
        for (int mi = 0; mi < 4; ++mi) {
            const int r0 = m0 + wm * 64 + mi * 16 + qr;
#pragma unroll
            for (int nj = 0; nj < 4; ++nj) {
                const int c = colBase + nj * 8 + qc;
                float v0 = acc[mi][nj][0] + bv[2*nj];
                float v1 = acc[mi][nj][1] + bv[2*nj+1];
                float v2 = acc[mi][nj][2] + bv[2*nj];
                float v3 = acc[mi][nj][3] + bv[2*nj+1];
                if (!sel) {
                    v0 = 1.f / (1.f + __expf(-v0));
                    v1 = 1.f / (1.f + __expf(-v1));
                    v2 = 1.f / (1.f + __expf(-v2));
                    v3 = 1.f / (1.f + __expf(-v3));
                } else if (rz) {
                    v0 = tanhf(v0); v1 = tanhf(v1);
                    v2 = tanhf(v2); v3 = tanhf(v3);
                }
                *(__half2*)(Cout + (size_t)r0 * ldC + c) =
                    __halves2half2(__float2half_rn(v0), __float2half_rn(v1));
                *(__half2*)(Cout + (size_t)(r0 + 8) * ldC + c) =
                    __halves2half2(__float2half_rn(v2), __float2half_rn(v3));
            }
        }
    } else {
        float* Cout = (float*)out0v;
#pragma unroll
        for (int mi = 0; mi < 4; ++mi) {
            const int r0 = m0 + wm * 64 + mi * 16 + qr;
            const int r1 = r0 + 8;
            float h0v[8], h1v[8];
#pragma unroll
            for (int nj = 0; nj < 4; ++nj) {
                const int c = gcol0 + nj * 8 + qc;
                float2 t0 = __half22float2(*(const __half2*)(hsrc + (size_t)r0 * ldC + c));
                float2 t1 = __half22float2(*(const __half2*)(hsrc + (size_t)r1 * ldC + c));
                h0v[2*nj] = t0.x; h0v[2*nj+1] = t0.y;
                h1v[2*nj] = t1.x; h1v[2*nj+1] = t1.y;
            }
            float mx0 = h0v[0], mx1 = h1v[0];
#pragma unroll
            for (int k = 1; k < 8; ++k) {
                mx0 = fmaxf(mx0, h0v[k]);
                mx1 = fmaxf(mx1, h1v[k]);
            }
            mx0 = fmaxf(mx0, __shfl_xor_sync(0xffffffffu, mx0, 1));
            mx0 = fmaxf(mx0, __shfl_xor_sync(0xffffffffu, mx0, 2));
            mx1 = fmaxf(mx1, __shfl_xor_sync(0xffffffffu, mx1, 1));
            mx1 = fmaxf(mx1, __shfl_xor_sync(0xffffffffu, mx1, 2));
            float s0 = 0.f, s1 = 0.f;
#pragma unroll
            for (int k = 0; k < 8; ++k) {
                h0v[k] = __expf(h0v[k] - mx0); s0 += h0v[k];
                h1v[k] = __expf(h1v[k] - mx1); s1 += h1v[k];
            }
            s0 += __shfl_xor_sync(0xffffffffu, s0, 1);
            s0 += __shfl_xor_sync(0xffffffffu, s0, 2);
            s1 += __shfl_xor_sync(0xffffffffu, s1, 1);
            s1 += __shfl_xor_sync(0xffffffffu, s1, 2);
            const float inv0 = 1.f / s0, inv1 = 1.f / s1;
#pragma unroll
            for (int nj = 0; nj < 4; ++nj) {
                const int c = gcol0 + nj * 8 + qc;
                float y0 = acc[mi][nj][0], y1 = acc[mi][nj][1];
                float y2 = acc[mi][nj][2], y3 = acc[mi][nj][3];
                float v0 = (h0v[2*nj]   * inv0) * (y0 / (1.f + __expf(-y0)));
                float v1 = (h0v[2*nj+1] * inv0) * (y1 / (1.f + __expf(-y1)));
                float v2 = (h1v[2*nj]   * inv1) * (y2 / (1.f + __expf(-y2)));
                float v3 = (h1v[2*nj+1] * inv1) * (y3 / (1.f + __expf(-y3)));
                __stcs((float2*)(Cout + (size_t)r0 * ldC + c), make_float2(v0, v1));
                __stcs((float2*)(Cout + (size_t)r1 * ldC + c), make_float2(v2, v3));
            }
        }
    }
}

// ---------------------------------------------------------------------------
// Scan: parallel fast path when r_h == 0 (linear recurrence), else sequential.
// tc = tanh(cand) is precomputed by GEMM0's epilogue -> scans are pure fma.
// ---------------------------------------------------------------------------

// Phase 1: per-chunk affine composition (A,B): h_end = A*h_start + B
__global__ void scan_part1(const __half* __restrict__ delta,
                           const __half* __restrict__ tc,
                           float* __restrict__ Abuf,
                           float* __restrict__ Bbuf,
                           int BD, int CHK)
{
    if (!g_rh_zero) return;
    const int l2 = blockIdx.x * blockDim.x + threadIdx.x;
    const int cc = blockIdx.y;
    const int BD2 = BD >> 1;
    const __half2* dp = (const __half2*)delta + (size_t)cc * CHK * BD2 + l2;
    const __half2* cp = (const __half2*)tc    + (size_t)cc * CHK * BD2 + l2;
    float Ax = 1.f, Ay = 1.f, Bx = 0.f, By = 0.f;
#pragma unroll 8
    for (int u = 0; u < CHK; ++u) {
        float2 d = __half22float2(dp[(size_t)u * BD2]);
        float2 t = __half22float2(cp[(size_t)u * BD2]);
        float ax = 1.f - d.x, ay = 1.f - d.y;
        Ax *= ax; Ay *= ay;
        Bx = fmaf(ax, Bx, d.x * t.x);
        By = fmaf(ay, By, d.y * t.y);
    }
    *(float2*)(Abuf + (size_t)cc * BD + 2 * l2) = make_float2(Ax, Ay);
    *(float2*)(Bbuf + (size_t)cc * BD + 2 * l2) = make_float2(Bx, By);
}

// Phase 2 (fast path): boundary scan, all NCHK (A,B) prefetched to registers.
// Fallback path (r_h != 0): full sequential scan folded in (same BD lanes).
__global__ void scan_part2(const float* __restrict__ Abuf,
                           const float* __restrict__ Bbuf,
                           const float* __restrict__ h0,
                           float* __restrict__ hb,
                           float* __restrict__ h_all,
                           const __half* __restrict__ delta,
                           const __half* __restrict__ cand,
                           const float* __restrict__ r_h,
                           __half* __restrict__ hhi,
                           int BD, int NCHK, int T, int D)
{
    const int lane = blockIdx.x * blockDim.x + threadIdx.x;
    if (g_rh_zero) {
        float h = h0[lane];
        h_all[lane] = h;
        if (NCHK <= 32) {
            float Ar[32], Br[32];
#pragma unroll
            for (int cc = 0; cc < 32; ++cc) {
                if (cc < NCHK) {
                    Ar[cc] = Abuf[(size_t)cc * BD + lane];
                    Br[cc] = Bbuf[(size_t)cc * BD + lane];
                }
            }
#pragma unroll
            for (int cc = 0; cc < 32; ++cc) {
                if (cc < NCHK) {
                    hb[(size_t)cc * BD + lane] = h;
                    h = fmaf(Ar[cc], h, Br[cc]);
                }
            }
        } else {
            for (int cc = 0; cc < NCHK; ++cc) {
                hb[(size_t)cc * BD + lane] = h;
                h = fmaf(Abuf[(size_t)cc * BD + lane], h, Bbuf[(size_t)cc * BD + lane]);
            }
        }
    } else {
        float h = h0[lane];
        float rh = r_h[lane % D];
        h_all[lane] = h;
        for (int t = 0; t < T; ++t) {
            float d = __half2float(delta[(size_t)t * BD + lane]);
            float c = __half2float(cand[(size_t)t * BD + lane]);
            float cv = tanhf(fmaf(rh, h, c));
            h = fmaf(d, cv - h, h);
            h_all[BD + (size_t)t * BD + lane] = h;
            hhi[(size_t)t * BD + lane] = __float2half_rn(h);
        }
    }
}

// Phase 3: recompute within chunk from boundary, write h_all fp32 + h fp16
__global__ void scan_part3(const __half* __restrict__ delta,
                           const __half* __restrict__ tc,
                           const float* __restrict__ hb,
                           float* __restrict__ h_all,
                           __half* __restrict__ hhi,
                           int BD, int CHK)
{
    if (!g_rh_zero) return;
    const int l2 = blockIdx.x * blockDim.x + threadIdx.x;
    const int cc = blockIdx.y;
    const int BD2 = BD >> 1;
    const __half2* dp = (const __half2*)delta + (size_t)cc * CHK * BD2 + l2;
    const __half2* cp = (const __half2*)tc    + (size_t)cc * CHK * BD2 + l2;
    __half2* hp16 = (__half2*)hhi + (size_t)cc * CHK * BD2 + l2;
    float2* hp32 = (float2*)(h_all + BD) + (size_t)cc * CHK * BD2 + l2;
    float2 h = *(const float2*)(hb + (size_t)cc * BD + 2 * l2);
#pragma unroll 8
    for (int u = 0; u < CHK; ++u) {
        float2 d = __half22float2(__ldcs(dp + (size_t)u * BD2));
        float2 t = __half22float2(__ldcs(cp + (size_t)u * BD2));
        h.x = fmaf(d.x, t.x - h.x, h.x);
        h.y = fmaf(d.y, t.y - h.y, h.y);
        __stcs(hp32 + (size_t)u * BD2, h);
        hp16[(size_t)u * BD2] = __halves2half2(__float2half_rn(h.x), __float2half_rn(h.y));
    }
}

// ---------------------------------------------------------------------------
extern "C" void kernel_launch(void* const* d_in, const int* in_sizes, int n_in,
                              void* d_out, int out_size)
{
    const float* x       = (const float*)d_in[0];
    const float* h0      = (const float*)d_in[1];
    const float* W_x     = (const float*)d_in[2];
    const float* r_h     = (const float*)d_in[3];
    const float* b       = (const float*)d_in[4];
    const float* W_delta = (const float*)d_in[5];
    const float* b_delta = (const float*)d_in[6];
    const float* W_out   = (const float*)d_in[7];
    float* out = (float*)d_out;

    int D  = (int)(sqrt((double)in_sizes[2]) + 0.5);
    int Bn = in_sizes[1] / D;
    int Tn = in_sizes[0] / (Bn * D);
    int BD = Bn * D;
    int M  = Tn * Bn;
    int DD = D * D;

    float *ghall, *gA, *gB, *ghb;
    __half *gdh, *gch, *xh, *hh, *wh, *woh;
    cudaGetSymbolAddress((void**)&gdh,   g_dh);
    cudaGetSymbolAddress((void**)&gch,   g_ch);
    cudaGetSymbolAddress((void**)&ghall, g_hall);
    cudaGetSymbolAddress((void**)&xh,    g_xh);
    cudaGetSymbolAddress((void**)&hh,    g_hh);
    cudaGetSymbolAddress((void**)&wh,    g_wh);
    cudaGetSymbolAddress((void**)&woh,   g_woh);
    cudaGetSymbolAddress((void**)&gA,    g_Abuf);
    cudaGetSymbolAddress((void**)&gB,    g_Bbuf);
    cudaGetSymbolAddress((void**)&ghb,   g_hb);

    float *hall, *outs;
    long need_both = (long)(Tn + 1) * BD + (long)M * D;
    if ((long)out_size >= need_both) {
        hall = out;
        outs = out + (size_t)(Tn + 1) * BD;
    } else {
        hall = ghall;
        outs = out;
    }

    cudaFuncSetAttribute(gemm_f16<0>, cudaFuncAttributeMaxDynamicSharedMemorySize, GSMEM);
    cudaFuncSetAttribute(gemm_f16<1>, cudaFuncAttributeMaxDynamicSharedMemorySize, GSMEM);

    // Phase 0: one fused conversion launch (2 float4/thread; r_h flag in block 0)
    int n4x = (M * D) / 4;
    int n4w = DD / 4;
    int n4tot = n4x + 3 * n4w;
    int half_n = (n4tot + 1) / 2;
    cvt_all<<<(half_n + 255) / 256, 256>>>(x, W_delta, W_x, W_out, r_h,
                                           xh, wh, woh, n4x, n4w, D, half_n);

    // Phase 1: fused delta|tc GEMM (N = 2D, split at D), fp16 outputs
    gemm_f16<0><<<dim3(2 * D / 128, M / 128), 256, GSMEM>>>(
        xh, wh, b_delta, b, gdh, gch, nullptr, D, D, D);

    // Phase 2: scan — parallel chunked fast path (r_h==0); sequential fallback
    // folded into scan_part2.
    {
        int CHK = 64;
        while (Tn % CHK) CHK >>= 1;
        int NCHK = Tn / CHK;
        if (NCHK > MAX_NCHK) { CHK = Tn / MAX_NCHK; NCHK = MAX_NCHK; }
        dim3 gch2(BD / 512, NCHK);          // 2 lanes per thread
        scan_part1<<<gch2, 256>>>(gdh, gch, gA, gB, BD, CHK);
        scan_part2<<<BD / 256, 256>>>(gA, gB, h0, ghb, hall,
                                      gdh, gch, r_h, hh, BD, NCHK, Tn, D);
        scan_part3<<<gch2, 256>>>(gdh, gch, ghb, hall, hh, BD, CHK);
    }

    // Phase 3: output GEMM with fused compete-softmax + silu epilogue
    gemm_f16<1><<<dim3(D / 128, M / 128), 256, GSMEM>>>(
        hh, woh, nullptr, nullptr, outs, nullptr, hh, D, D, 0);
}